// round 4
// baseline (speedup 1.0000x reference)
#include <cuda_runtime.h>
#include <cuda_fp16.h>

// Fixed shapes: N=10000 nodes, E=320000 edges, node_dim=out_dim=128, init_dim=257.
#define DIM 128
#define MAX_N 10016
#define NEG_SLOPE 0.01f

// Static scratch (no allocation allowed)
__device__ __half  g_P1h[MAX_N * DIM];      // fp16: atom @ (W1a+W2)^T
__device__ __half  g_P2h[MAX_N * DIM];      // fp16: atom @ (W1b+W2)^T
// k-pair packed transposed weights: g_At2[k2*128+o] = (At[2k2][o], At[2k2+1][o])
__device__ float2  g_At2[(DIM / 2) * DIM];
__device__ float2  g_Bt2[(DIM / 2) * DIM];
__device__ float   g_wc[DIM];               // W1[:,256]
__device__ float   g_bias[DIM];             // b1 + b2

// ---- f32x2 packed-FMA helpers (Blackwell PTX) -----------------------------
__device__ __forceinline__ unsigned long long pack2(float x, float y) {
    unsigned long long r;
    asm("mov.b64 %0, {%1, %2};" : "=l"(r) : "f"(x), "f"(y));
    return r;
}
__device__ __forceinline__ void unpack2(unsigned long long v, float& x, float& y) {
    asm("mov.b64 {%0, %1}, %2;" : "=f"(x), "=f"(y) : "l"(v));
}
__device__ __forceinline__ void ffma2(unsigned long long& d,
                                      unsigned long long a, unsigned long long b) {
    asm("fma.rn.f32x2 %0, %1, %2, %0;" : "+l"(d) : "l"(a), "l"(b));
}

// ---------------------------------------------------------------------------
// Kernel 0: combine + transpose + k-pair-pack weights.
// blockIdx = o (output col, 0..127), threadIdx = k (0..127). Coalesced loads.
// ---------------------------------------------------------------------------
__global__ void prep_weights(const float* __restrict__ W1,
                             const float* __restrict__ b1,
                             const float* __restrict__ W2,
                             const float* __restrict__ b2) {
    const int o = blockIdx.x;
    const int k = threadIdx.x;
    const float w2 = W2[o * DIM + k];
    const float a = W1[o * 257 + k]       + w2;
    const float b = W1[o * 257 + DIM + k] + w2;
    // scatter into float2 components: element (k/2, o), component (k&1)
    reinterpret_cast<float*>(g_At2)[(k >> 1) * (2 * DIM) + o * 2 + (k & 1)] = a;
    reinterpret_cast<float*>(g_Bt2)[(k >> 1) * (2 * DIM) + o * 2 + (k & 1)] = b;
    if (k == 0) {
        g_wc[o]   = W1[o * 257 + 256];
        g_bias[o] = b1[o] + b2[o];
    }
}

// ---------------------------------------------------------------------------
// Kernel 1: node projections, packed f32x2 FMA, 32 nodes (16 pairs)/block.
// Thread t owns output column o=t. Inner loop over k-pairs:
//   2x LDG.64 (weights) + 16x LDS.128 (node-pair data, broadcast) + 64 ffma2.
// ---------------------------------------------------------------------------
#define NPB   32
#define NPAIR (NPB / 2)
__global__ void __launch_bounds__(128) node_proj(const float* __restrict__ atom, int N) {
    __shared__ float2 sP[NPAIR][DIM];   // sP[j][k] = (atom[2j][k], atom[2j+1][k])
    const int base = blockIdx.x * NPB;
    const int t = threadIdx.x;          // 0..127 = output column o

    #pragma unroll
    for (int j = 0; j < NPAIR; j++) {
        int n0 = base + 2 * j, n1 = n0 + 1;
        float v0 = (n0 < N) ? atom[n0 * DIM + t] : 0.0f;
        float v1 = (n1 < N) ? atom[n1 * DIM + t] : 0.0f;
        sP[j][t] = make_float2(v0, v1);
    }
    __syncthreads();

    unsigned long long acc1[NPAIR], acc2[NPAIR];
    #pragma unroll
    for (int j = 0; j < NPAIR; j++) { acc1[j] = 0ull; acc2[j] = 0ull; }

    const int o = t;
    #pragma unroll 2
    for (int k2 = 0; k2 < DIM / 2; k2++) {
        const float2 wa = g_At2[k2 * DIM + o];   // coalesced, L1/L2-resident
        const float2 wb = g_Bt2[k2 * DIM + o];
        const unsigned long long aa0 = pack2(wa.x, wa.x);
        const unsigned long long aa1 = pack2(wa.y, wa.y);
        const unsigned long long bb0 = pack2(wb.x, wb.x);
        const unsigned long long bb1 = pack2(wb.y, wb.y);
        #pragma unroll
        for (int j = 0; j < NPAIR; j++) {
            // one LDS.128 broadcast: (n0[k], n1[k], n0[k+1], n1[k+1])
            const ulonglong2 v =
                *reinterpret_cast<const ulonglong2*>(&sP[j][2 * k2]);
            ffma2(acc1[j], v.x, aa0);
            ffma2(acc1[j], v.y, aa1);
            ffma2(acc2[j], v.x, bb0);
            ffma2(acc2[j], v.y, bb1);
        }
    }

    #pragma unroll
    for (int j = 0; j < NPAIR; j++) {
        const int n0 = base + 2 * j, n1 = n0 + 1;
        float p0, p1, q0, q1;
        unpack2(acc1[j], p0, p1);
        unpack2(acc2[j], q0, q1);
        // writes into [N, MAX_N) padding are harmless (never gathered)
        g_P1h[n0 * DIM + o] = __float2half_rn(p0);
        g_P2h[n0 * DIM + o] = __float2half_rn(q0);
        g_P1h[n1 * DIM + o] = __float2half_rn(p1);
        g_P2h[n1 * DIM + o] = __float2half_rn(q1);
    }
}

// ---------------------------------------------------------------------------
// Kernel 2: edge gather (fp16) + add + leaky_relu -> f32 streaming stores.
// One warp per 8 edges; lane covers 4 output columns (uint2 = 8B per table).
// Indices/bond loaded via broadcast int4/float4, gathers front-batched (MLP 16).
// ---------------------------------------------------------------------------
#define EPW 8
__device__ __forceinline__ float lrelu(float x) {
    return x > 0.0f ? x : NEG_SLOPE * x;
}

__global__ void __launch_bounds__(256) edge_kernel(const float* __restrict__ bond,
                            const int* __restrict__ src,
                            const int* __restrict__ dst,
                            float* __restrict__ out, int E) {
    const int lane = threadIdx.x & 31;
    const int warp = threadIdx.x >> 5;
    const int wpb  = blockDim.x >> 5;

    const float4 wc4 = reinterpret_cast<const float4*>(g_wc)[lane];
    const float4 bs4 = reinterpret_cast<const float4*>(g_bias)[lane];

    const uint2* __restrict__ P1 = reinterpret_cast<const uint2*>(g_P1h);
    const uint2* __restrict__ P2 = reinterpret_cast<const uint2*>(g_P2h);
    float4* __restrict__ O = reinterpret_cast<float4*>(out);

    const int e0 = (blockIdx.x * wpb + warp) * EPW;
    if (e0 >= E) return;

    if (e0 + EPW <= E) {
        // fast path: vector-broadcast index/bond loads
        const int4 s0 = *reinterpret_cast<const int4*>(src + e0);
        const int4 s1 = *reinterpret_cast<const int4*>(src + e0 + 4);
        const int4 d0 = *reinterpret_cast<const int4*>(dst + e0);
        const int4 d1 = *reinterpret_cast<const int4*>(dst + e0 + 4);
        const float4 b0 = *reinterpret_cast<const float4*>(bond + e0);
        const float4 b1 = *reinterpret_cast<const float4*>(bond + e0 + 4);
        const int   s[EPW]  = {s0.x, s0.y, s0.z, s0.w, s1.x, s1.y, s1.z, s1.w};
        const int   d[EPW]  = {d0.x, d0.y, d0.z, d0.w, d1.x, d1.y, d1.z, d1.w};
        const float bw[EPW] = {b0.x, b0.y, b0.z, b0.w, b1.x, b1.y, b1.z, b1.w};

        uint2 pu[EPW], qu[EPW];
        #pragma unroll
        for (int i = 0; i < EPW; i++) {
            pu[i] = __ldg(&P1[s[i] * (DIM / 4) + lane]);
            qu[i] = __ldg(&P2[d[i] * (DIM / 4) + lane]);
        }
        #pragma unroll
        for (int i = 0; i < EPW; i++) {
            const float2 pa = __half22float2(*reinterpret_cast<__half2*>(&pu[i].x));
            const float2 pb = __half22float2(*reinterpret_cast<__half2*>(&pu[i].y));
            const float2 qa = __half22float2(*reinterpret_cast<__half2*>(&qu[i].x));
            const float2 qb = __half22float2(*reinterpret_cast<__half2*>(&qu[i].y));
            float4 r;
            r.x = lrelu(pa.x + qa.x + fmaf(bw[i], wc4.x, bs4.x));
            r.y = lrelu(pa.y + qa.y + fmaf(bw[i], wc4.y, bs4.y));
            r.z = lrelu(pb.x + qb.x + fmaf(bw[i], wc4.z, bs4.z));
            r.w = lrelu(pb.y + qb.y + fmaf(bw[i], wc4.w, bs4.w));
            __stcs(&O[(e0 + i) * (DIM / 4) + lane], r);
        }
    } else {
        for (int e = e0; e < E; e++) {
            const int s = __ldg(src + e);
            const int d = __ldg(dst + e);
            const float bw = __ldg(bond + e);
            uint2 pu = __ldg(&P1[s * (DIM / 4) + lane]);
            uint2 qu = __ldg(&P2[d * (DIM / 4) + lane]);
            const float2 pa = __half22float2(*reinterpret_cast<__half2*>(&pu.x));
            const float2 pb = __half22float2(*reinterpret_cast<__half2*>(&pu.y));
            const float2 qa = __half22float2(*reinterpret_cast<__half2*>(&qu.x));
            const float2 qb = __half22float2(*reinterpret_cast<__half2*>(&qu.y));
            float4 r;
            r.x = lrelu(pa.x + qa.x + fmaf(bw, wc4.x, bs4.x));
            r.y = lrelu(pa.y + qa.y + fmaf(bw, wc4.y, bs4.y));
            r.z = lrelu(pb.x + qb.x + fmaf(bw, wc4.z, bs4.z));
            r.w = lrelu(pb.y + qb.y + fmaf(bw, wc4.w, bs4.w));
            __stcs(&O[e * (DIM / 4) + lane], r);
        }
    }
}

// ---------------------------------------------------------------------------
// Launcher. Inputs: 0 atom[N,128] 1 bond[E,1] 2 src[E] 3 dst[E]
//                   4 W1[128,257] 5 b1[128] 6 W2[128,128] 7 b2[128]
// Output: [E,128] f32
// ---------------------------------------------------------------------------
extern "C" void kernel_launch(void* const* d_in, const int* in_sizes, int n_in,
                              void* d_out, int out_size) {
    const float* atom = (const float*)d_in[0];
    const float* bond = (const float*)d_in[1];
    const int*   src  = (const int*)d_in[2];
    const int*   dst  = (const int*)d_in[3];
    const float* W1   = (const float*)d_in[4];
    const float* b1   = (const float*)d_in[5];
    const float* W2   = (const float*)d_in[6];
    const float* b2   = (const float*)d_in[7];
    float* out = (float*)d_out;

    const int N = in_sizes[0] / DIM;
    const int E = in_sizes[2];

    prep_weights<<<DIM, DIM>>>(W1, b1, W2, b2);
    node_proj<<<(N + NPB - 1) / NPB, DIM>>>(atom, N);

    const int threads = 256;                          // 8 warps/block
    const int edges_per_block = (threads / 32) * EPW; // 64
    edge_kernel<<<(E + edges_per_block - 1) / edges_per_block, threads>>>(
        bond, src, dst, out, E);
}

// round 5
// speedup vs baseline: 1.5017x; 1.5017x over previous
#include <cuda_runtime.h>
#include <cuda_fp16.h>

// Fixed shapes: N=10000 nodes, E=320000 edges, node_dim=out_dim=128, init_dim=257.
#define DIM 128
#define MAX_N 10016
#define NEG_SLOPE 0.01f

// Static scratch (no allocation allowed)
__device__ __half g_P1h[MAX_N * DIM];   // fp16: atom @ (W1a+W2)^T
__device__ __half g_P2h[MAX_N * DIM];   // fp16: atom @ (W1b+W2)^T
// Combined weights in mma.sync m16n8k16 B-fragment layout (fp16):
//   index = ((kt*16 + nt)*32 + lane)*4 + slot,  kt in 0..7, nt in 0..15
//   lane = (n%8)*4 + ((k%16)%8)/2 ; slot = ((k%16)>=8)*2 + (k&1)
__device__ __half g_WAf[8 * 16 * 32 * 4];   // W1a + W2   (32 KB)
__device__ __half g_WBf[8 * 16 * 32 * 4];   // W1b + W2   (32 KB)
__device__ float  g_wc[DIM];                // W1[:,256]
__device__ float  g_bias[DIM];              // b1 + b2

// ---------------------------------------------------------------------------
// Kernel 0: combine weights + emit fp16 B-fragments. block = o, thread = k.
// Loads coalesced; scattered 2B stores are fire-and-forget (tiny volume).
// ---------------------------------------------------------------------------
__global__ void prep_weights(const float* __restrict__ W1,
                             const float* __restrict__ b1,
                             const float* __restrict__ W2,
                             const float* __restrict__ b2) {
    const int o = blockIdx.x;    // output col n, 0..127
    const int k = threadIdx.x;   // input feature, 0..127
    const float w2 = W2[o * DIM + k];
    const float wa = W1[o * 257 + k]       + w2;
    const float wb = W1[o * 257 + DIM + k] + w2;

    const int kt   = k >> 4;
    const int r    = k & 15;
    const int tig  = (r & 7) >> 1;
    const int lane = (o & 7) * 4 + tig;
    const int slot = ((r >= 8) ? 2 : 0) + (r & 1);
    const int nt   = o >> 3;
    const int idx  = ((kt * 16 + nt) * 32 + lane) * 4 + slot;
    g_WAf[idx] = __float2half_rn(wa);
    g_WBf[idx] = __float2half_rn(wb);

    if (k == 0) {
        g_wc[o]   = W1[o * 257 + 256];
        g_bias[o] = b1[o] + b2[o];
    }
}

// ---------------------------------------------------------------------------
// Kernel 1: node projections on tensor cores (mma.sync m16n8k16 f16->f32).
// Block = 128 threads (4 warps), one m16 row-tile per block.
// Warp w covers n columns [w*32, w*32+32) (4 n8-tiles) for BOTH tables.
// ---------------------------------------------------------------------------
#define SA_STRIDE 136   // halves per row: 272B -> LDS bank-conflict-free frags

__device__ __forceinline__ void mma16816(float* c, const unsigned* a, uint2 b) {
    asm volatile(
        "mma.sync.aligned.m16n8k16.row.col.f32.f16.f16.f32 "
        "{%0,%1,%2,%3}, {%4,%5,%6,%7}, {%8,%9}, {%0,%1,%2,%3};"
        : "+f"(c[0]), "+f"(c[1]), "+f"(c[2]), "+f"(c[3])
        : "r"(a[0]), "r"(a[1]), "r"(a[2]), "r"(a[3]), "r"(b.x), "r"(b.y));
}

__global__ void __launch_bounds__(128) node_mma(const float* __restrict__ atom, int N) {
    __shared__ __half sA[16 * SA_STRIDE];   // m16 x k128 fp16, padded rows
    const int t    = threadIdx.x;
    const int base = blockIdx.x * 16;

    // Fill A tile: thread t -> row t/8, 16 cols starting at (t%8)*16.
    {
        const int r  = t >> 3;
        const int c0 = (t & 7) * 16;
        const int n  = base + r;
        __half* dstp = &sA[r * SA_STRIDE + c0];
        if (n < N) {
            const float4* srcp = reinterpret_cast<const float4*>(atom + n * DIM + c0);
            #pragma unroll
            for (int i = 0; i < 4; i++) {
                const float4 v = srcp[i];
                reinterpret_cast<__half2*>(dstp)[2 * i]     = __floats2half2_rn(v.x, v.y);
                reinterpret_cast<__half2*>(dstp)[2 * i + 1] = __floats2half2_rn(v.z, v.w);
            }
        } else {
            #pragma unroll
            for (int i = 0; i < 8; i++)
                reinterpret_cast<__half2*>(dstp)[i] = __floats2half2_rn(0.f, 0.f);
        }
    }
    __syncthreads();

    const int lane = t & 31;
    const int w    = t >> 5;        // warp id -> n-slice
    const int g    = lane >> 2;     // group (row within m16)
    const int tig  = lane & 3;

    float c1[4][4], c2[4][4];
    #pragma unroll
    for (int j = 0; j < 4; j++)
        #pragma unroll
        for (int i = 0; i < 4; i++) { c1[j][i] = 0.f; c2[j][i] = 0.f; }

    const uint2* __restrict__ WA = reinterpret_cast<const uint2*>(g_WAf);
    const uint2* __restrict__ WB = reinterpret_cast<const uint2*>(g_WBf);

    #pragma unroll
    for (int kt = 0; kt < 8; kt++) {
        const int k0 = kt * 16 + tig * 2;
        unsigned a[4];
        a[0] = *reinterpret_cast<const unsigned*>(&sA[g * SA_STRIDE + k0]);
        a[1] = *reinterpret_cast<const unsigned*>(&sA[(g + 8) * SA_STRIDE + k0]);
        a[2] = *reinterpret_cast<const unsigned*>(&sA[g * SA_STRIDE + k0 + 8]);
        a[3] = *reinterpret_cast<const unsigned*>(&sA[(g + 8) * SA_STRIDE + k0 + 8]);

        #pragma unroll
        for (int j = 0; j < 4; j++) {
            const int nt  = w * 4 + j;
            const int fidx = (kt * 16 + nt) * 32 + lane;
            const uint2 bA = __ldg(&WA[fidx]);
            const uint2 bB = __ldg(&WB[fidx]);
            mma16816(c1[j], a, bA);
            mma16816(c2[j], a, bB);
        }
    }

    // Store: c0,c1 -> row base+g ; c2,c3 -> row base+g+8 ; cols nt*8 + tig*2.
    const int r0 = base + g, r1 = base + g + 8;
    #pragma unroll
    for (int j = 0; j < 4; j++) {
        const int col = (w * 4 + j) * 8 + tig * 2;
        if (r0 < N) {
            *reinterpret_cast<__half2*>(&g_P1h[r0 * DIM + col]) = __floats2half2_rn(c1[j][0], c1[j][1]);
            *reinterpret_cast<__half2*>(&g_P2h[r0 * DIM + col]) = __floats2half2_rn(c2[j][0], c2[j][1]);
        }
        if (r1 < N) {
            *reinterpret_cast<__half2*>(&g_P1h[r1 * DIM + col]) = __floats2half2_rn(c1[j][2], c1[j][3]);
            *reinterpret_cast<__half2*>(&g_P2h[r1 * DIM + col]) = __floats2half2_rn(c2[j][2], c2[j][3]);
        }
    }
}

// ---------------------------------------------------------------------------
// Kernel 2: edge gather (fp16) + add + leaky_relu -> f32 streaming stores.
// (R3 configuration: EPW=4, 256 threads — measured best.)
// ---------------------------------------------------------------------------
#define EPW 4
__device__ __forceinline__ float lrelu(float x) {
    return x > 0.0f ? x : NEG_SLOPE * x;
}

__global__ void __launch_bounds__(256) edge_kernel(const float* __restrict__ bond,
                            const int* __restrict__ src,
                            const int* __restrict__ dst,
                            float* __restrict__ out, int E) {
    const int lane = threadIdx.x & 31;
    const int warp = threadIdx.x >> 5;
    const int wpb  = blockDim.x >> 5;

    const float4 wc4 = reinterpret_cast<const float4*>(g_wc)[lane];
    const float4 bs4 = reinterpret_cast<const float4*>(g_bias)[lane];

    const uint2* __restrict__ P1 = reinterpret_cast<const uint2*>(g_P1h);
    const uint2* __restrict__ P2 = reinterpret_cast<const uint2*>(g_P2h);
    float4* __restrict__ O = reinterpret_cast<float4*>(out);

    const int e0 = (blockIdx.x * wpb + warp) * EPW;

    #pragma unroll
    for (int i = 0; i < EPW; i++) {
        const int e = e0 + i;
        if (e >= E) return;
        const int s = __ldg(src + e);
        const int d = __ldg(dst + e);
        const float bw = __ldg(bond + e);

        uint2 pu = __ldg(&P1[s * (DIM / 4) + lane]);
        uint2 qu = __ldg(&P2[d * (DIM / 4) + lane]);
        const float2 pa = __half22float2(*reinterpret_cast<__half2*>(&pu.x));
        const float2 pb = __half22float2(*reinterpret_cast<__half2*>(&pu.y));
        const float2 qa = __half22float2(*reinterpret_cast<__half2*>(&qu.x));
        const float2 qb = __half22float2(*reinterpret_cast<__half2*>(&qu.y));

        float4 r;
        r.x = lrelu(pa.x + qa.x + fmaf(bw, wc4.x, bs4.x));
        r.y = lrelu(pa.y + qa.y + fmaf(bw, wc4.y, bs4.y));
        r.z = lrelu(pb.x + qb.x + fmaf(bw, wc4.z, bs4.z));
        r.w = lrelu(pb.y + qb.y + fmaf(bw, wc4.w, bs4.w));

        __stcs(&O[e * (DIM / 4) + lane], r);   // streaming: keep P tables in L2
    }
}

// ---------------------------------------------------------------------------
// Launcher. Inputs: 0 atom[N,128] 1 bond[E,1] 2 src[E] 3 dst[E]
//                   4 W1[128,257] 5 b1[128] 6 W2[128,128] 7 b2[128]
// Output: [E,128] f32
// ---------------------------------------------------------------------------
extern "C" void kernel_launch(void* const* d_in, const int* in_sizes, int n_in,
                              void* d_out, int out_size) {
    const float* atom = (const float*)d_in[0];
    const float* bond = (const float*)d_in[1];
    const int*   src  = (const int*)d_in[2];
    const int*   dst  = (const int*)d_in[3];
    const float* W1   = (const float*)d_in[4];
    const float* b1   = (const float*)d_in[5];
    const float* W2   = (const float*)d_in[6];
    const float* b2   = (const float*)d_in[7];
    float* out = (float*)d_out;

    const int N = in_sizes[0] / DIM;
    const int E = in_sizes[2];

    prep_weights<<<DIM, DIM>>>(W1, b1, W2, b2);
    node_mma<<<(N + 15) / 16, 128>>>(atom, N);

    const int threads = 256;                          // 8 warps/block
    const int edges_per_block = (threads / 32) * EPW; // 32
    edge_kernel<<<(E + edges_per_block - 1) / edges_per_block, threads>>>(
        bond, src, dst, out, E);
}